// round 6
// baseline (speedup 1.0000x reference)
#include <cuda_runtime.h>
#include <cuda_bf16.h>
#include <cstdint>

typedef unsigned long long ull;

// ---------------- scratch (device globals; no allocation allowed) ----------------
__device__ float g_pooled[512 * 90];
__device__ float g_X[512 * 4096];
__device__ float g_Ypart[64 * 512 * 128];   // split-K partials for fc7||fcast
__device__ float g_A1[512 * 256];           // Wih1@emb + bih1 + bhh1
__device__ float g_AF1[512 * 256];          // Wih1@fcast + bih1 + bhh1
__device__ float g_h1[512 * 64];
__device__ float g_c1[512 * 64];
__device__ float g_h2[512 * 32];
__device__ float g_c2[512 * 32];
// transposed weights [k][r] for coalesced matvec reads
__device__ float g_WT1[64 * 256];    // Whh1^T
__device__ float g_WTih1[64 * 256];  // Wih1^T
__device__ float g_WTI2[64 * 128];   // Wih2^T
__device__ float g_WTH2[32 * 128];   // Whh2^T

// ---------------- helpers ----------------
__device__ __forceinline__ unsigned enc_f(float f) {
    unsigned u = __float_as_uint(f);
    return (u & 0x80000000u) ? ~u : (u | 0x80000000u);
}
__device__ __forceinline__ float dec_f(unsigned k) {
    return __uint_as_float((k & 0x80000000u) ? (k ^ 0x80000000u) : ~k);
}
// overflow-safe, clamp-free activations (error ~1e-7)
__device__ __forceinline__ float sigf(float x) {
    return __fdividef(1.f, 1.f + __expf(-x));
}
__device__ __forceinline__ float tanh_f(float x) {
    float ax = fabsf(x);
    float e = __expf(-2.f * ax);
    float t = __fdividef(1.f - e, 1.f + e);
    return copysignf(t, x);
}
// packed f32x2 ops (FFMA2 path — only reachable via PTX)
__device__ __forceinline__ ull fma2(ull a, ull b, ull c) {
    ull d;
    asm("fma.rn.f32x2 %0, %1, %2, %3;" : "=l"(d) : "l"(a), "l"(b), "l"(c));
    return d;
}
__device__ __forceinline__ ull add2(ull a, ull b) {
    ull d;
    asm("add.rn.f32x2 %0, %1, %2;" : "=l"(d) : "l"(a), "l"(b));
    return d;
}
__device__ __forceinline__ float hsum2(ull a) {
    float x, y;
    asm("mov.b64 {%0, %1}, %2;" : "=f"(x), "=f"(y) : "l"(a));
    return x + y;
}

// ---------------- K1: SPP pooling (+ folded weight transpose in first CTAs) ----------------
// grid 1536 (= 512 frames * 3 channels), block 256
__global__ void spp_kernel(const float* __restrict__ frames, float* __restrict__ pooled,
                           const float* __restrict__ Whh1, const float* __restrict__ Wih1,
                           const float* __restrict__ Wih2, const float* __restrict__ Whh2) {
    __shared__ unsigned cm[144];   // 12x12 grid of 16x16-block maxes, encoded
    int tid = threadIdx.x;
    int b = blockIdx.x;

    // folded transpose: first 64 CTAs also emit the [k][r] weight copies
    if (b < 64) {
        int t = b * 256 + tid;
        {
            int r = t >> 6, k = t & 63;
            g_WT1[k * 256 + r] = Whh1[t];
            g_WTih1[k * 256 + r] = Wih1[t];
        }
        if (t < 8192) {
            int r = t >> 6, k = t & 63;
            g_WTI2[k * 128 + r] = Wih2[t];
        }
        if (t < 4096) {
            int r = t >> 5, k = t & 31;
            g_WTH2[k * 128 + r] = Whh2[t];
        }
    }

    int s = b / 3;
    int c = b - s * 3;
    if (tid < 144) cm[tid] = 0u;
    __syncthreads();

    const float4* base = reinterpret_cast<const float4*>(frames + (size_t)b * 36864);
    for (int seg = tid; seg < 2304; seg += 256) {
        const float4* p = base + seg * 4;
        float4 a = p[0], b4 = p[1], c4 = p[2], d4 = p[3];
        float m = fmaxf(fmaxf(fmaxf(a.x, a.y), fmaxf(a.z, a.w)),
                        fmaxf(fmaxf(b4.x, b4.y), fmaxf(b4.z, b4.w)));
        m = fmaxf(m, fmaxf(fmaxf(c4.x, c4.y), fmaxf(c4.z, c4.w)));
        m = fmaxf(m, fmaxf(fmaxf(d4.x, d4.y), fmaxf(d4.z, d4.w)));
        int row = seg / 12;
        int wc = seg - row * 12;
        int cell = (row >> 4) * 12 + wc;
        atomicMax(&cm[cell], enc_f(m));
    }
    __syncthreads();

    if (tid < 30) {
        unsigned m = 0u;
        int off;
        if (tid < 16) {
            int i = tid >> 2, j = tid & 3;
            for (int r = 3 * i; r < 3 * i + 3; r++)
                for (int q = 3 * j; q < 3 * j + 3; q++)
                    m = max(m, cm[r * 12 + q]);
            off = c * 16 + tid;
        } else if (tid < 25) {
            int t2 = tid - 16, i = t2 / 3, j = t2 - 3 * (t2 / 3);
            for (int r = 4 * i; r < 4 * i + 4; r++)
                for (int q = 4 * j; q < 4 * j + 4; q++)
                    m = max(m, cm[r * 12 + q]);
            off = 48 + c * 9 + t2;
        } else if (tid < 29) {
            int t2 = tid - 25, i = t2 >> 1, j = t2 & 1;
            for (int r = 6 * i; r < 6 * i + 6; r++)
                for (int q = 6 * j; q < 6 * j + 6; q++)
                    m = max(m, cm[r * 12 + q]);
            off = 75 + c * 4 + t2;
        } else {
            for (int r = 0; r < 144; r++) m = max(m, cm[r]);
            off = 87 + c;
        }
        pooled[s * 90 + off] = dec_f(m);
    }
}

// ---------------- K2: X = relu(pooled @ W_spp^T + b_spp) ----------------
__global__ void gemm1_kernel(const float* __restrict__ pooled,
                             const float* __restrict__ Wspp,
                             const float* __restrict__ bspp,
                             float* __restrict__ X) {
    __shared__ float Ps[90][32];
    __shared__ float Ws[90][64];
    int tid = threadIdx.x;
    int e0 = blockIdx.x * 64;
    int s0 = blockIdx.y * 32;

    for (int idx = tid; idx < 2880; idx += 256) {
        int k = idx >> 5, si = idx & 31;
        Ps[k][si] = pooled[(s0 + si) * 90 + k];
    }
    for (int idx = tid; idx < 5760; idx += 256) {
        int k = idx >> 6, e = idx & 63;
        Ws[k][e] = Wspp[(size_t)(e0 + e) * 90 + k];
    }
    __syncthreads();

    int ex = tid & 63, sg = tid >> 6;
    float acc[8];
#pragma unroll
    for (int j = 0; j < 8; j++) acc[j] = 0.f;
    for (int k = 0; k < 90; k++) {
        float w = Ws[k][ex];
#pragma unroll
        for (int j = 0; j < 8; j++) acc[j] += w * Ps[k][sg * 8 + j];
    }
    float bias = bspp[e0 + ex];
#pragma unroll
    for (int j = 0; j < 8; j++) {
        int s = s0 + sg * 8 + j;
        X[(size_t)s * 4096 + e0 + ex] = fmaxf(acc[j] + bias, 0.f);
    }
}

// ---------------- K3: split-K GEMM for [emb | fcast] pre-activation ----------------
// grid (64 k-splits, 8 s-tiles), block 256; each block: 64 s x 128 j over K=64
__global__ void gemm2_kernel(const float* __restrict__ X,
                             const float* __restrict__ Wfc7,
                             const float* __restrict__ Wfcast,
                             float* __restrict__ Ypart) {
    __shared__ float Xs[64][36];
    __shared__ float Ws2[32][128];
    int tid = threadIdx.x;
    int ks = blockIdx.x;
    int s0 = blockIdx.y * 64;
    int k0 = ks * 64;
    int tx = tid & 15, ty = tid >> 4;

    float acc[4][8];
#pragma unroll
    for (int j = 0; j < 4; j++)
#pragma unroll
        for (int u = 0; u < 8; u++) acc[j][u] = 0.f;

    for (int kc = 0; kc < 64; kc += 32) {
        __syncthreads();
        for (int idx = tid; idx < 512; idx += 256) {
            int si = idx >> 3, kv = idx & 7;
            float4 v = *reinterpret_cast<const float4*>(
                &X[(size_t)(s0 + si) * 4096 + k0 + kc + kv * 4]);
            *reinterpret_cast<float4*>(&Xs[si][kv * 4]) = v;
        }
        for (int idx = tid; idx < 1024; idx += 256) {
            int e = idx >> 3, kv = idx & 7;
            const float* wrow = (e < 64) ? (Wfc7 + (size_t)e * 4096)
                                         : (Wfcast + (size_t)(e - 64) * 4096);
            float4 w = *reinterpret_cast<const float4*>(&wrow[k0 + kc + kv * 4]);
            Ws2[kv * 4 + 0][e] = w.x;
            Ws2[kv * 4 + 1][e] = w.y;
            Ws2[kv * 4 + 2][e] = w.z;
            Ws2[kv * 4 + 3][e] = w.w;
        }
        __syncthreads();
#pragma unroll 8
        for (int k = 0; k < 32; k++) {
            float xa[4];
#pragma unroll
            for (int j = 0; j < 4; j++) xa[j] = Xs[ty * 4 + j][k];
            float4 w0 = *reinterpret_cast<const float4*>(&Ws2[k][tx * 8]);
            float4 w1 = *reinterpret_cast<const float4*>(&Ws2[k][tx * 8 + 4]);
            float wb[8] = {w0.x, w0.y, w0.z, w0.w, w1.x, w1.y, w1.z, w1.w};
#pragma unroll
            for (int j = 0; j < 4; j++)
#pragma unroll
                for (int u = 0; u < 8; u++) acc[j][u] += xa[j] * wb[u];
        }
    }
#pragma unroll
    for (int j = 0; j < 4; j++)
#pragma unroll
        for (int u = 0; u < 8; u++) {
            int s = s0 + ty * 4 + j;
            Ypart[((size_t)ks * 512 + s) * 128 + tx * 8 + u] = acc[j][u];
        }
}

// ---------------- K4: reduce partials, relu, project through Wih1^T (coalesced) ----------------
// grid 512 (one per step), block 256
__global__ void proj_kernel(const float* __restrict__ Ypart,
                            const float* __restrict__ bfc7,
                            const float* __restrict__ bfcast,
                            const float* __restrict__ bih1,
                            const float* __restrict__ bhh1,
                            float* __restrict__ A1, float* __restrict__ AF1) {
    __shared__ float xe[64], xf[64];
    int tid = threadIdx.x;
    int s = blockIdx.x;
    if (tid < 128) {
        float a = (tid < 64) ? bfc7[tid] : bfcast[tid - 64];
#pragma unroll
        for (int p = 0; p < 64; p++)
            a += Ypart[((size_t)p * 512 + s) * 128 + tid];
        a = fmaxf(a, 0.f);
        if (tid < 64) xe[tid] = a; else xf[tid - 64] = a;
    }
    __syncthreads();
    int r = tid;
    float a = bih1[r] + bhh1[r];
    float af = a;
#pragma unroll 8
    for (int k = 0; k < 64; k++) {
        float w = g_WTih1[k * 256 + r];   // coalesced across threads
        a += w * xe[k];
        af += w * xf[k];
    }
    A1[s * 256 + r] = a;
    AF1[s * 256 + r] = af;
}

// ---------------- K5: decoupled sequential scan ----------------
// Threads 0..127 (L1): cell1, 2 gate-rows/thread, pair (even,odd)=(i,f)/(g,o)
// Threads 128..255 (L2): cell2, consumes h1(j) same generation
// Barrier protocol (count-matched per generation):
//   bar 2 (256): L1 arrives after publishing h1(i); L2 syncs before consuming h1(j).
//   bar 3 (256): L2 arrives right after its matvec finished READING h1(j);
//                L1 syncs at top of iter i>=1 (slot reuse guard + L1-internal ordering).
__global__ void __launch_bounds__(256, 1)
lstm_kernel(const float* __restrict__ Whh1,
            const float* __restrict__ Wih2,
            const float* __restrict__ Whh2,
            const float* __restrict__ bih2,
            const float* __restrict__ bhh2) {
    __shared__ __align__(16) float h1ring[2][64];
    __shared__ __align__(16) float h2buf[2][32];

    int t = threadIdx.x;
    if (t < 64) h1ring[1][t] = 0.f;                 // h1(-1)
    if (t >= 64 && t < 96) h2buf[1][t - 64] = 0.f;  // h2(-1)
    __syncthreads();

    if (t < 128) {
        // ---- L1: cell1; 2 rows/thread of Whh1, packed f32x2, LDS.128 h loads ----
        int p = t >> 1;
        int odd = t & 1;
        int rA = odd ? (64 + p) : p;          // f_p : i_p
        int rB = odd ? (192 + p) : (128 + p); // o_p : g_p
        ull wA[32], wB[32];
        const ull* WA = reinterpret_cast<const ull*>(Whh1 + (size_t)rA * 64);
        const ull* WB = reinterpret_cast<const ull*>(Whh1 + (size_t)rB * 64);
#pragma unroll
        for (int k = 0; k < 32; k++) { wA[k] = WA[k]; wB[k] = WB[k]; }
        float c1 = 0.f;
        float a1A0 = g_A1[rA],       a1B0 = g_A1[rB];
        float a1A1 = g_A1[256 + rA], a1B1 = g_A1[256 + rB];

        for (int i = 0; i < 512; i++) {
            if (i) asm volatile("bar.sync 3, 256;" ::: "memory");
            const ulonglong2* hv =
                reinterpret_cast<const ulonglong2*>(h1ring[(i + 1) & 1]);
            ull sA0 = 0ull, sA1 = 0ull, sA2 = 0ull, sA3 = 0ull;
            ull sB0 = 0ull, sB1 = 0ull, sB2 = 0ull, sB3 = 0ull;
#pragma unroll
            for (int k = 0; k < 16; k += 2) {
                ulonglong2 h0 = hv[k];
                ulonglong2 h1 = hv[k + 1];
                sA0 = fma2(wA[2 * k], h0.x, sA0);     sA1 = fma2(wA[2 * k + 1], h0.y, sA1);
                sB0 = fma2(wB[2 * k], h0.x, sB0);     sB1 = fma2(wB[2 * k + 1], h0.y, sB1);
                sA2 = fma2(wA[2 * k + 2], h1.x, sA2); sA3 = fma2(wA[2 * k + 3], h1.y, sA3);
                sB2 = fma2(wB[2 * k + 2], h1.x, sB2); sB3 = fma2(wB[2 * k + 3], h1.y, sB3);
            }
            float own0 = hsum2(add2(add2(sA0, sA1), add2(sA2, sA3))) + a1A0;
            float own1 = hsum2(add2(add2(sB0, sB1), add2(sB2, sB3))) + a1B0;
            a1A0 = a1A1; a1B0 = a1B1;
            if (i + 2 < 512) {
                a1A1 = __ldg(&g_A1[(i + 2) * 256 + rA]);
                a1B1 = __ldg(&g_A1[(i + 2) * 256 + rB]);
            }
            float p0 = __shfl_xor_sync(0xffffffffu, own0, 1);
            float p1 = __shfl_xor_sync(0xffffffffu, own1, 1);
            if (!odd) {
                float iv = sigf(own0), gv = tanh_f(own1);
                float fv = sigf(p0), ov = sigf(p1);
                c1 = fv * c1 + iv * gv;
                float h1n = ov * tanh_f(c1);
                h1ring[i & 1][p] = h1n;
                g_h1[i * 64 + p] = h1n;
                g_c1[i * 64 + p] = c1;
            }
            asm volatile("bar.arrive 2, 256;" ::: "memory");  // publish h1(i)
        }
    } else {
        // ---- L2: cell2; 1 row/thread, packed f32x2, LDS.128 loads ----
        int u = t - 128;
        int v = u >> 2;   // element 0..31
        int q = u & 3;    // gate 0..3 (i,f,g,o)
        int r2 = q * 32 + v;
        ull wI[32], wH[16];
        const ull* WI = reinterpret_cast<const ull*>(Wih2 + (size_t)r2 * 64);
        const ull* WH = reinterpret_cast<const ull*>(Whh2 + (size_t)r2 * 32);
#pragma unroll
        for (int k = 0; k < 32; k++) wI[k] = WI[k];
#pragma unroll
        for (int k = 0; k < 16; k++) wH[k] = WH[k];
        float b2 = bih2[r2] + bhh2[r2];
        float c2 = 0.f;

        for (int j = 0; j < 512; j++) {
            asm volatile("bar.sync 2, 256;" ::: "memory");    // wait h1(j)
            const ulonglong2* h1v =
                reinterpret_cast<const ulonglong2*>(h1ring[j & 1]);
            const ulonglong2* h2v =
                reinterpret_cast<const ulonglong2*>(h2buf[(j + 1) & 1]); // h2(j-1)
            ull s0 = 0ull, s1 = 0ull, s2 = 0ull, s3 = 0ull;
#pragma unroll
            for (int k = 0; k < 8; k += 2) {
                ulonglong2 h0 = h2v[k];
                ulonglong2 h1 = h2v[k + 1];
                s0 = fma2(wH[2 * k], h0.x, s0);     s1 = fma2(wH[2 * k + 1], h0.y, s1);
                s2 = fma2(wH[2 * k + 2], h1.x, s2); s3 = fma2(wH[2 * k + 3], h1.y, s3);
            }
#pragma unroll
            for (int k = 0; k < 16; k += 2) {
                ulonglong2 h0 = h1v[k];
                ulonglong2 h1 = h1v[k + 1];
                s0 = fma2(wI[2 * k], h0.x, s0);     s1 = fma2(wI[2 * k + 1], h0.y, s1);
                s2 = fma2(wI[2 * k + 2], h1.x, s2); s3 = fma2(wI[2 * k + 3], h1.y, s3);
            }
            asm volatile("bar.arrive 3, 256;" ::: "memory");  // done reading h1(j)
            float g2 = hsum2(add2(add2(s0, s1), add2(s2, s3))) + b2;
            float gb = __shfl_xor_sync(0xffffffffu, g2, 1);
            float gc = __shfl_xor_sync(0xffffffffu, g2, 2);
            float gd = __shfl_xor_sync(0xffffffffu, gb, 2);
            if (q == 0) {
                float iv = sigf(g2), fv = sigf(gb);
                float gv = tanh_f(gc), ov = sigf(gd);
                c2 = fv * c2 + iv * gv;
                float h2n = ov * tanh_f(c2);
                h2buf[j & 1][v] = h2n;   // read at iter j+1 (ordered via bar 2)
                g_h2[j * 32 + v] = h2n;
                g_c2[j * 32 + v] = c2;
            }
        }
    }
}

// ---------------- K6: batched forecast cells + both output heads ----------------
// grid 512 (one per step), block 256; all weight reads coalesced via transposed copies
__global__ void post_kernel(const float* __restrict__ bih2,
                            const float* __restrict__ bhh2,
                            const float* __restrict__ Wfc8,
                            const float* __restrict__ bfc8,
                            float* __restrict__ out) {
    __shared__ float sh1[64], sh2[32], sfh1[64];
    __shared__ float sg[256], sg2[128];
    int t = threadIdx.x;
    int s = blockIdx.x;
    if (t < 64) sh1[t] = g_h1[s * 64 + t];
    else if (t < 96) sh2[t - 64] = g_h2[s * 32 + (t - 64)];
    __syncthreads();

    // fcell1 gates: AF1 already holds Wih1@fx + bih1 + bhh1
    {
        float a = g_AF1[s * 256 + t];
#pragma unroll 8
        for (int k = 0; k < 64; k++)
            a += g_WT1[k * 256 + t] * sh1[k];
        sg[t] = a;
    }
    __syncthreads();
    if (t < 64) {
        float iv = sigf(sg[t]), fv = sigf(sg[64 + t]);
        float gv = tanh_f(sg[128 + t]), ov = sigf(sg[192 + t]);
        float cf = fv * g_c1[s * 64 + t] + iv * gv;
        sfh1[t] = ov * tanh_f(cf);
    }
    __syncthreads();

    // fcell2 gates
    if (t < 128) {
        float a = bih2[t] + bhh2[t];
#pragma unroll 8
        for (int k = 0; k < 64; k++)
            a += g_WTI2[k * 128 + t] * sfh1[k];
#pragma unroll 8
        for (int k = 0; k < 32; k++)
            a += g_WTH2[k * 128 + t] * sh2[k];
        sg2[t] = a;
    }
    __syncthreads();
    if (t < 32) {
        float iv = sigf(sg2[t]), fv = sigf(sg2[32 + t]);
        float gv = tanh_f(sg2[64 + t]), ov = sigf(sg2[96 + t]);
        float cf = fv * g_c2[s * 32 + t] + iv * gv;
        float fh2 = ov * tanh_f(cf);
        float w = Wfc8[t];
        float pd = w * sh2[t];
        float fd = w * fh2;
#pragma unroll
        for (int o = 16; o; o >>= 1) {
            pd += __shfl_down_sync(0xffffffffu, pd, o);
            fd += __shfl_down_sync(0xffffffffu, fd, o);
        }
        if (t == 0) {
            float b8 = bfc8[0];
            out[s] = sigf(pd + b8);
            out[512 + s] = sigf(fd + b8);
        }
    }
}

// ---------------- launch ----------------
extern "C" void kernel_launch(void* const* d_in, const int* in_sizes, int n_in,
                              void* d_out, int out_size) {
    const float* frames = (const float*)d_in[0];
    const float* W_spp  = (const float*)d_in[1];
    const float* b_spp  = (const float*)d_in[2];
    const float* W_fc7  = (const float*)d_in[3];
    const float* b_fc7  = (const float*)d_in[4];
    const float* W_fcast= (const float*)d_in[5];
    const float* b_fcast= (const float*)d_in[6];
    const float* Wih1   = (const float*)d_in[7];
    const float* Whh1   = (const float*)d_in[8];
    const float* bih1   = (const float*)d_in[9];
    const float* bhh1   = (const float*)d_in[10];
    const float* Wih2   = (const float*)d_in[11];
    const float* Whh2   = (const float*)d_in[12];
    const float* bih2   = (const float*)d_in[13];
    const float* bhh2   = (const float*)d_in[14];
    const float* W_fc8  = (const float*)d_in[15];
    const float* b_fc8  = (const float*)d_in[16];
    float* out = (float*)d_out;

    float *p_pooled, *p_X, *p_Ypart, *p_A1, *p_AF1;
    cudaGetSymbolAddress((void**)&p_pooled, g_pooled);
    cudaGetSymbolAddress((void**)&p_X, g_X);
    cudaGetSymbolAddress((void**)&p_Ypart, g_Ypart);
    cudaGetSymbolAddress((void**)&p_A1, g_A1);
    cudaGetSymbolAddress((void**)&p_AF1, g_AF1);

    spp_kernel<<<1536, 256>>>(frames, p_pooled, Whh1, Wih1, Wih2, Whh2);
    gemm1_kernel<<<dim3(64, 16), 256>>>(p_pooled, W_spp, b_spp, p_X);
    gemm2_kernel<<<dim3(64, 8), 256>>>(p_X, W_fc7, W_fcast, p_Ypart);
    proj_kernel<<<512, 256>>>(p_Ypart, b_fc7, b_fcast, bih1, bhh1, p_A1, p_AF1);
    lstm_kernel<<<1, 256>>>(Whh1, Wih2, Whh2, bih2, bhh2);
    post_kernel<<<512, 256>>>(bih2, bhh2, W_fc8, b_fc8, out);
}

// round 7
// speedup vs baseline: 1.1963x; 1.1963x over previous
#include <cuda_runtime.h>
#include <cuda_bf16.h>
#include <cstdint>

typedef unsigned long long ull;

// ---------------- scratch (device globals; no allocation allowed) ----------------
__device__ float g_pooled[512 * 90];
__device__ float g_X[512 * 4096];
__device__ float g_Ypart[32 * 512 * 128];   // split-K partials for fc7||fcast
__device__ float g_A1[512 * 256];           // Wih1@emb + bih1 + bhh1
__device__ float g_AF1[512 * 256];          // Wih1@fcast + bih1 + bhh1
__device__ float g_h1[512 * 64];
__device__ float g_c1[512 * 64];
__device__ float g_h2[512 * 32];
__device__ float g_c2[512 * 32];
// transposed weights [k][r] for coalesced matvec reads
__device__ float g_WT1[64 * 256];    // Whh1^T
__device__ float g_WTih1[64 * 256];  // Wih1^T
__device__ float g_WTI2[64 * 128];   // Wih2^T
__device__ float g_WTH2[32 * 128];   // Whh2^T

// ---------------- helpers ----------------
__device__ __forceinline__ unsigned enc_f(float f) {
    unsigned u = __float_as_uint(f);
    return (u & 0x80000000u) ? ~u : (u | 0x80000000u);
}
__device__ __forceinline__ float dec_f(unsigned k) {
    return __uint_as_float((k & 0x80000000u) ? (k ^ 0x80000000u) : ~k);
}
// hardware tanh (MUFU.TANH, ~16cy, max abs err ~5e-4) — replaces exp+div chains
__device__ __forceinline__ float tanha(float x) {
    float y;
    asm("tanh.approx.f32 %0, %1;" : "=f"(y) : "f"(x));
    return y;
}
__device__ __forceinline__ float sigf(float x) {
    return fmaf(tanha(0.5f * x), 0.5f, 0.5f);   // sigmoid(x) = 0.5*(1+tanh(x/2))
}
// packed f32x2 ops (FFMA2 path — only reachable via PTX)
__device__ __forceinline__ ull fma2(ull a, ull b, ull c) {
    ull d;
    asm("fma.rn.f32x2 %0, %1, %2, %3;" : "=l"(d) : "l"(a), "l"(b), "l"(c));
    return d;
}
__device__ __forceinline__ ull add2(ull a, ull b) {
    ull d;
    asm("add.rn.f32x2 %0, %1, %2;" : "=l"(d) : "l"(a), "l"(b));
    return d;
}
__device__ __forceinline__ float hsum2(ull a) {
    float x, y;
    asm("mov.b64 {%0, %1}, %2;" : "=f"(x), "=f"(y) : "l"(a));
    return x + y;
}

// ---------------- K1: SPP pooling (+ folded weight transpose in first CTAs) ----------------
// grid 1536 (= 512 frames * 3 channels), block 256
__global__ void spp_kernel(const float* __restrict__ frames, float* __restrict__ pooled,
                           const float* __restrict__ Whh1, const float* __restrict__ Wih1,
                           const float* __restrict__ Wih2, const float* __restrict__ Whh2) {
    __shared__ unsigned cm[144];   // 12x12 grid of 16x16-block maxes, encoded
    int tid = threadIdx.x;
    int b = blockIdx.x;

    // folded transpose: first 64 CTAs also emit the [k][r] weight copies
    if (b < 64) {
        int t = b * 256 + tid;
        {
            int r = t >> 6, k = t & 63;
            g_WT1[k * 256 + r] = Whh1[t];
            g_WTih1[k * 256 + r] = Wih1[t];
        }
        if (t < 8192) {
            int r = t >> 6, k = t & 63;
            g_WTI2[k * 128 + r] = Wih2[t];
        }
        if (t < 4096) {
            int r = t >> 5, k = t & 31;
            g_WTH2[k * 128 + r] = Whh2[t];
        }
    }

    int s = b / 3;
    int c = b - s * 3;
    if (tid < 144) cm[tid] = 0u;
    __syncthreads();

    const float4* base = reinterpret_cast<const float4*>(frames + (size_t)b * 36864);
    for (int seg = tid; seg < 2304; seg += 256) {
        const float4* p = base + seg * 4;
        float4 a = p[0], b4 = p[1], c4 = p[2], d4 = p[3];
        float m = fmaxf(fmaxf(fmaxf(a.x, a.y), fmaxf(a.z, a.w)),
                        fmaxf(fmaxf(b4.x, b4.y), fmaxf(b4.z, b4.w)));
        m = fmaxf(m, fmaxf(fmaxf(c4.x, c4.y), fmaxf(c4.z, c4.w)));
        m = fmaxf(m, fmaxf(fmaxf(d4.x, d4.y), fmaxf(d4.z, d4.w)));
        int row = seg / 12;
        int wc = seg - row * 12;
        int cell = (row >> 4) * 12 + wc;
        atomicMax(&cm[cell], enc_f(m));
    }
    __syncthreads();

    if (tid < 30) {
        unsigned m = 0u;
        int off;
        if (tid < 16) {
            int i = tid >> 2, j = tid & 3;
            for (int r = 3 * i; r < 3 * i + 3; r++)
                for (int q = 3 * j; q < 3 * j + 3; q++)
                    m = max(m, cm[r * 12 + q]);
            off = c * 16 + tid;
        } else if (tid < 25) {
            int t2 = tid - 16, i = t2 / 3, j = t2 - 3 * (t2 / 3);
            for (int r = 4 * i; r < 4 * i + 4; r++)
                for (int q = 4 * j; q < 4 * j + 4; q++)
                    m = max(m, cm[r * 12 + q]);
            off = 48 + c * 9 + t2;
        } else if (tid < 29) {
            int t2 = tid - 25, i = t2 >> 1, j = t2 & 1;
            for (int r = 6 * i; r < 6 * i + 6; r++)
                for (int q = 6 * j; q < 6 * j + 6; q++)
                    m = max(m, cm[r * 12 + q]);
            off = 75 + c * 4 + t2;
        } else {
            for (int r = 0; r < 144; r++) m = max(m, cm[r]);
            off = 87 + c;
        }
        pooled[s * 90 + off] = dec_f(m);
    }
}

// ---------------- K2: X = relu(pooled @ W_spp^T + b_spp) ----------------
__global__ void gemm1_kernel(const float* __restrict__ pooled,
                             const float* __restrict__ Wspp,
                             const float* __restrict__ bspp,
                             float* __restrict__ X) {
    __shared__ float Ps[90][32];
    __shared__ float Ws[90][64];
    int tid = threadIdx.x;
    int e0 = blockIdx.x * 64;
    int s0 = blockIdx.y * 32;

    for (int idx = tid; idx < 2880; idx += 256) {
        int k = idx >> 5, si = idx & 31;
        Ps[k][si] = pooled[(s0 + si) * 90 + k];
    }
    for (int idx = tid; idx < 5760; idx += 256) {
        int k = idx >> 6, e = idx & 63;
        Ws[k][e] = Wspp[(size_t)(e0 + e) * 90 + k];
    }
    __syncthreads();

    int ex = tid & 63, sg = tid >> 6;
    float acc[8];
#pragma unroll
    for (int j = 0; j < 8; j++) acc[j] = 0.f;
    for (int k = 0; k < 90; k++) {
        float w = Ws[k][ex];
#pragma unroll
        for (int j = 0; j < 8; j++) acc[j] += w * Ps[k][sg * 8 + j];
    }
    float bias = bspp[e0 + ex];
#pragma unroll
    for (int j = 0; j < 8; j++) {
        int s = s0 + sg * 8 + j;
        X[(size_t)s * 4096 + e0 + ex] = fmaxf(acc[j] + bias, 0.f);
    }
}

// ---------------- K3: split-K GEMM for [emb | fcast] pre-activation ----------------
// grid (32 k-splits, 8 s-tiles), block 256; each block: 64 s x 128 j over K=128
__global__ void gemm2_kernel(const float* __restrict__ X,
                             const float* __restrict__ Wfc7,
                             const float* __restrict__ Wfcast,
                             float* __restrict__ Ypart) {
    __shared__ float Xs[64][36];
    __shared__ float Ws2[32][128];
    int tid = threadIdx.x;
    int ks = blockIdx.x;
    int s0 = blockIdx.y * 64;
    int k0 = ks * 128;
    int tx = tid & 15, ty = tid >> 4;

    float acc[4][8];
#pragma unroll
    for (int j = 0; j < 4; j++)
#pragma unroll
        for (int u = 0; u < 8; u++) acc[j][u] = 0.f;

    for (int kc = 0; kc < 128; kc += 32) {
        __syncthreads();
        for (int idx = tid; idx < 512; idx += 256) {
            int si = idx >> 3, kv = idx & 7;
            float4 v = *reinterpret_cast<const float4*>(
                &X[(size_t)(s0 + si) * 4096 + k0 + kc + kv * 4]);
            *reinterpret_cast<float4*>(&Xs[si][kv * 4]) = v;
        }
        for (int idx = tid; idx < 1024; idx += 256) {
            int e = idx >> 3, kv = idx & 7;
            const float* wrow = (e < 64) ? (Wfc7 + (size_t)e * 4096)
                                         : (Wfcast + (size_t)(e - 64) * 4096);
            float4 w = *reinterpret_cast<const float4*>(&wrow[k0 + kc + kv * 4]);
            Ws2[kv * 4 + 0][e] = w.x;
            Ws2[kv * 4 + 1][e] = w.y;
            Ws2[kv * 4 + 2][e] = w.z;
            Ws2[kv * 4 + 3][e] = w.w;
        }
        __syncthreads();
#pragma unroll 8
        for (int k = 0; k < 32; k++) {
            float xa[4];
#pragma unroll
            for (int j = 0; j < 4; j++) xa[j] = Xs[ty * 4 + j][k];
            float4 w0 = *reinterpret_cast<const float4*>(&Ws2[k][tx * 8]);
            float4 w1 = *reinterpret_cast<const float4*>(&Ws2[k][tx * 8 + 4]);
            float wb[8] = {w0.x, w0.y, w0.z, w0.w, w1.x, w1.y, w1.z, w1.w};
#pragma unroll
            for (int j = 0; j < 4; j++)
#pragma unroll
                for (int u = 0; u < 8; u++) acc[j][u] += xa[j] * wb[u];
        }
    }
#pragma unroll
    for (int j = 0; j < 4; j++)
#pragma unroll
        for (int u = 0; u < 8; u++) {
            int s = s0 + ty * 4 + j;
            Ypart[((size_t)ks * 512 + s) * 128 + tx * 8 + u] = acc[j][u];
        }
}

// ---------------- K4: reduce partials, relu, project through Wih1^T (coalesced) ----------------
// grid 512 (one per step), block 256
__global__ void proj_kernel(const float* __restrict__ Ypart,
                            const float* __restrict__ bfc7,
                            const float* __restrict__ bfcast,
                            const float* __restrict__ bih1,
                            const float* __restrict__ bhh1,
                            float* __restrict__ A1, float* __restrict__ AF1) {
    __shared__ float xe[64], xf[64];
    int tid = threadIdx.x;
    int s = blockIdx.x;
    if (tid < 128) {
        float a = (tid < 64) ? bfc7[tid] : bfcast[tid - 64];
#pragma unroll
        for (int p = 0; p < 32; p++)
            a += Ypart[((size_t)p * 512 + s) * 128 + tid];
        a = fmaxf(a, 0.f);
        if (tid < 64) xe[tid] = a; else xf[tid - 64] = a;
    }
    __syncthreads();
    int r = tid;
    float a = bih1[r] + bhh1[r];
    float af = a;
#pragma unroll 8
    for (int k = 0; k < 64; k++) {
        float w = g_WTih1[k * 256 + r];   // coalesced across threads
        a += w * xe[k];
        af += w * xf[k];
    }
    A1[s * 256 + r] = a;
    AF1[s * 256 + r] = af;
}

// ---------------- K5: sequential scan (R5 barrier structure + LDS.128 + MUFU.TANH) ----------------
// Threads 0..127 : cell1, 2 gate-rows/thread; pair (even,odd) = (i,f)/(g,o) for element p
// Threads 128..255: cell2, one step behind (cell1(i) || cell2(i-1)), 1 row/thread
#define BAR256() asm volatile("bar.sync 0, 256;" ::: "memory")

__global__ void __launch_bounds__(256, 1)
lstm_kernel(const float* __restrict__ Whh1,
            const float* __restrict__ Wih2,
            const float* __restrict__ Whh2,
            const float* __restrict__ bih2,
            const float* __restrict__ bhh2) {
    __shared__ __align__(16) float h1buf[2][64];
    __shared__ __align__(16) float h2buf[2][32];

    int t = threadIdx.x;
    if (t < 64) { h1buf[0][t] = 0.f; h1buf[1][t] = 0.f; }
    if (t >= 64 && t < 96) { h2buf[0][t - 64] = 0.f; h2buf[1][t - 64] = 0.f; }

    if (t < 128) {
        // ---- L1: cell1; 2 rows/thread of Whh1, packed f32x2 ----
        int p = t >> 1;
        int odd = t & 1;
        int rA = odd ? (64 + p) : p;          // f_p : i_p
        int rB = odd ? (192 + p) : (128 + p); // o_p : g_p
        ull wA[32], wB[32];
        const ull* WA = reinterpret_cast<const ull*>(Whh1 + (size_t)rA * 64);
        const ull* WB = reinterpret_cast<const ull*>(Whh1 + (size_t)rB * 64);
#pragma unroll
        for (int k = 0; k < 32; k++) { wA[k] = WA[k]; wB[k] = WB[k]; }
        float c1 = 0.f;
        // depth-2 prefetch pipeline for the input projection
        float a1A0 = g_A1[rA],       a1B0 = g_A1[rB];
        float a1A1 = g_A1[256 + rA], a1B1 = g_A1[256 + rB];
        BAR256();

        for (int i = 0; i < 513; i++) {
            if (i < 512) {
                int rd = (i & 1) ^ 1, wr = i & 1;
                const ulonglong2* hv = reinterpret_cast<const ulonglong2*>(h1buf[rd]);
                ull sA0 = 0ull, sA1 = 0ull, sA2 = 0ull, sA3 = 0ull;
                ull sB0 = 0ull, sB1 = 0ull, sB2 = 0ull, sB3 = 0ull;
#pragma unroll
                for (int k = 0; k < 16; k += 2) {
                    ulonglong2 h0 = hv[k];
                    ulonglong2 h1 = hv[k + 1];
                    sA0 = fma2(wA[2 * k], h0.x, sA0);     sA1 = fma2(wA[2 * k + 1], h0.y, sA1);
                    sB0 = fma2(wB[2 * k], h0.x, sB0);     sB1 = fma2(wB[2 * k + 1], h0.y, sB1);
                    sA2 = fma2(wA[2 * k + 2], h1.x, sA2); sA3 = fma2(wA[2 * k + 3], h1.y, sA3);
                    sB2 = fma2(wB[2 * k + 2], h1.x, sB2); sB3 = fma2(wB[2 * k + 3], h1.y, sB3);
                }
                // a1 accumulated LATE so the (L2-latency) prefetch has ~2 iterations of slack
                float own0 = hsum2(add2(add2(sA0, sA1), add2(sA2, sA3))) + a1A0;
                float own1 = hsum2(add2(add2(sB0, sB1), add2(sB2, sB3))) + a1B0;
                a1A0 = a1A1; a1B0 = a1B1;
                if (i + 2 < 512) {
                    a1A1 = __ldg(&g_A1[(i + 2) * 256 + rA]);
                    a1B1 = __ldg(&g_A1[(i + 2) * 256 + rB]);
                }
                float p0 = __shfl_xor_sync(0xffffffffu, own0, 1);
                float p1 = __shfl_xor_sync(0xffffffffu, own1, 1);
                if (!odd) {
                    float iv = sigf(own0), gv = tanha(own1);
                    float fv = sigf(p0), ov = sigf(p1);
                    c1 = fv * c1 + iv * gv;
                    float h1n = ov * tanha(c1);
                    h1buf[wr][p] = h1n;
                    g_h1[i * 64 + p] = h1n;
                    g_c1[i * 64 + p] = c1;
                }
            }
            BAR256();
        }
    } else {
        // ---- L2: cell2, one step behind; 1 row/thread, packed f32x2 ----
        int u = t - 128;
        int v = u >> 2;   // element 0..31
        int q = u & 3;    // gate 0..3 (i,f,g,o)
        int r2 = q * 32 + v;
        ull wI[32], wH[16];
        const ull* WI = reinterpret_cast<const ull*>(Wih2 + (size_t)r2 * 64);
        const ull* WH = reinterpret_cast<const ull*>(Whh2 + (size_t)r2 * 32);
#pragma unroll
        for (int k = 0; k < 32; k++) wI[k] = WI[k];
#pragma unroll
        for (int k = 0; k < 16; k++) wH[k] = WH[k];
        float b2 = bih2[r2] + bhh2[r2];
        float c2 = 0.f;
        BAR256();

        for (int i = 0; i < 513; i++) {
            if (i >= 1) {
                int j = i - 1;   // computing cell2(j): needs h1(j), h2(j-1)
                const ulonglong2* h1v = reinterpret_cast<const ulonglong2*>(h1buf[j & 1]);
                const ulonglong2* h2v = reinterpret_cast<const ulonglong2*>(h2buf[i & 1]);
                ull s0 = 0ull, s1 = 0ull, s2 = 0ull, s3 = 0ull;
#pragma unroll
                for (int k = 0; k < 8; k += 2) {
                    ulonglong2 h0 = h2v[k];
                    ulonglong2 h1 = h2v[k + 1];
                    s0 = fma2(wH[2 * k], h0.x, s0);     s1 = fma2(wH[2 * k + 1], h0.y, s1);
                    s2 = fma2(wH[2 * k + 2], h1.x, s2); s3 = fma2(wH[2 * k + 3], h1.y, s3);
                }
#pragma unroll
                for (int k = 0; k < 16; k += 2) {
                    ulonglong2 h0 = h1v[k];
                    ulonglong2 h1 = h1v[k + 1];
                    s0 = fma2(wI[2 * k], h0.x, s0);     s1 = fma2(wI[2 * k + 1], h0.y, s1);
                    s2 = fma2(wI[2 * k + 2], h1.x, s2); s3 = fma2(wI[2 * k + 3], h1.y, s3);
                }
                float g2 = hsum2(add2(add2(s0, s1), add2(s2, s3))) + b2;
                float gb = __shfl_xor_sync(0xffffffffu, g2, 1);
                float gc = __shfl_xor_sync(0xffffffffu, g2, 2);
                float gd = __shfl_xor_sync(0xffffffffu, gb, 2);
                if (q == 0) {
                    float iv = sigf(g2), fv = sigf(gb);
                    float gv = tanha(gc), ov = sigf(gd);
                    c2 = fv * c2 + iv * gv;
                    float h2n = ov * tanha(c2);
                    h2buf[(i & 1) ^ 1][v] = h2n;   // read back at iter i+1
                    g_h2[j * 32 + v] = h2n;
                    g_c2[j * 32 + v] = c2;
                }
            }
            BAR256();
        }
    }
}

// ---------------- K6: batched forecast cells + both output heads ----------------
// grid 512 (one per step), block 256; all weight reads coalesced via transposed copies
__global__ void post_kernel(const float* __restrict__ bih2,
                            const float* __restrict__ bhh2,
                            const float* __restrict__ Wfc8,
                            const float* __restrict__ bfc8,
                            float* __restrict__ out) {
    __shared__ float sh1[64], sh2[32], sfh1[64];
    __shared__ float sg[256], sg2[128];
    int t = threadIdx.x;
    int s = blockIdx.x;
    if (t < 64) sh1[t] = g_h1[s * 64 + t];
    else if (t < 96) sh2[t - 64] = g_h2[s * 32 + (t - 64)];
    __syncthreads();

    // fcell1 gates: AF1 already holds Wih1@fx + bih1 + bhh1
    {
        float a = g_AF1[s * 256 + t];
#pragma unroll 8
        for (int k = 0; k < 64; k++)
            a += g_WT1[k * 256 + t] * sh1[k];
        sg[t] = a;
    }
    __syncthreads();
    if (t < 64) {
        float iv = sigf(sg[t]), fv = sigf(sg[64 + t]);
        float gv = tanha(sg[128 + t]), ov = sigf(sg[192 + t]);
        float cf = fv * g_c1[s * 64 + t] + iv * gv;
        sfh1[t] = ov * tanha(cf);
    }
    __syncthreads();

    // fcell2 gates
    if (t < 128) {
        float a = bih2[t] + bhh2[t];
#pragma unroll 8
        for (int k = 0; k < 64; k++)
            a += g_WTI2[k * 128 + t] * sfh1[k];
#pragma unroll 8
        for (int k = 0; k < 32; k++)
            a += g_WTH2[k * 128 + t] * sh2[k];
        sg2[t] = a;
    }
    __syncthreads();
    if (t < 32) {
        float iv = sigf(sg2[t]), fv = sigf(sg2[32 + t]);
        float gv = tanha(sg2[64 + t]), ov = sigf(sg2[96 + t]);
        float cf = fv * g_c2[s * 32 + t] + iv * gv;
        float fh2 = ov * tanha(cf);
        float w = Wfc8[t];
        float pd = w * sh2[t];
        float fd = w * fh2;
#pragma unroll
        for (int o = 16; o; o >>= 1) {
            pd += __shfl_down_sync(0xffffffffu, pd, o);
            fd += __shfl_down_sync(0xffffffffu, fd, o);
        }
        if (t == 0) {
            float b8 = bfc8[0];
            out[s] = sigf(pd + b8);
            out[512 + s] = sigf(fd + b8);
        }
    }
}

// ---------------- launch ----------------
extern "C" void kernel_launch(void* const* d_in, const int* in_sizes, int n_in,
                              void* d_out, int out_size) {
    const float* frames = (const float*)d_in[0];
    const float* W_spp  = (const float*)d_in[1];
    const float* b_spp  = (const float*)d_in[2];
    const float* W_fc7  = (const float*)d_in[3];
    const float* b_fc7  = (const float*)d_in[4];
    const float* W_fcast= (const float*)d_in[5];
    const float* b_fcast= (const float*)d_in[6];
    const float* Wih1   = (const float*)d_in[7];
    const float* Whh1   = (const float*)d_in[8];
    const float* bih1   = (const float*)d_in[9];
    const float* bhh1   = (const float*)d_in[10];
    const float* Wih2   = (const float*)d_in[11];
    const float* Whh2   = (const float*)d_in[12];
    const float* bih2   = (const float*)d_in[13];
    const float* bhh2   = (const float*)d_in[14];
    const float* W_fc8  = (const float*)d_in[15];
    const float* b_fc8  = (const float*)d_in[16];
    float* out = (float*)d_out;

    float *p_pooled, *p_X, *p_Ypart, *p_A1, *p_AF1;
    cudaGetSymbolAddress((void**)&p_pooled, g_pooled);
    cudaGetSymbolAddress((void**)&p_X, g_X);
    cudaGetSymbolAddress((void**)&p_Ypart, g_Ypart);
    cudaGetSymbolAddress((void**)&p_A1, g_A1);
    cudaGetSymbolAddress((void**)&p_AF1, g_AF1);

    spp_kernel<<<1536, 256>>>(frames, p_pooled, Whh1, Wih1, Wih2, Whh2);
    gemm1_kernel<<<dim3(64, 16), 256>>>(p_pooled, W_spp, b_spp, p_X);
    gemm2_kernel<<<dim3(32, 8), 256>>>(p_X, W_fc7, W_fcast, p_Ypart);
    proj_kernel<<<512, 256>>>(p_Ypart, b_fc7, b_fcast, bih1, bhh1, p_A1, p_AF1);
    lstm_kernel<<<1, 256>>>(Whh1, Wih2, Whh2, bih2, bhh2);
    post_kernel<<<512, 256>>>(bih2, bhh2, W_fc8, b_fc8, out);
}